// round 7
// baseline (speedup 1.0000x reference)
#include <cuda_runtime.h>
#include <cstdint>

// out[i,p] = sum_{m,n} A[i,m] * B[i,n] * C[m,n,p]   (M1=M2=MP=5)
//
// Round-7 = round-3 base (direct strided float2 IO, EPT=2, 64-reg cap,
// 4 CTAs/SM) + packed f32x2 math: the two edges per thread are SIMD-paired
// into FFMA2 (sm_103a packed fp32 FMA), halving FMA issue slots 300->150
// per thread. C is stored DUPLICATED ({c,c} u64) in shared so packed
// constants load directly (LDS.128), no per-iteration packing.

#define M1 5
#define M2 5
#define MP 5
#define EPT 2
#define TPB 256

typedef unsigned long long u64;

__device__ __forceinline__ u64 pack2(float lo, float hi) {
    u64 r; asm("mov.b64 %0, {%1, %2};" : "=l"(r) : "f"(lo), "f"(hi)); return r;
}
__device__ __forceinline__ void unpack2(u64 v, float& lo, float& hi) {
    asm("mov.b64 {%0, %1}, %2;" : "=f"(lo), "=f"(hi) : "l"(v));
}
__device__ __forceinline__ u64 fma2(u64 a, u64 b, u64 c) {
    u64 r; asm("fma.rn.f32x2 %0, %1, %2, %3;" : "=l"(r) : "l"(a), "l"(b), "l"(c)); return r;
}
__device__ __forceinline__ u64 mul2(u64 a, u64 b) {
    u64 r; asm("mul.rn.f32x2 %0, %1, %2;" : "=l"(r) : "l"(a), "l"(b)); return r;
}

__global__ __launch_bounds__(TPB, 4)
void cg_combine_kernel(const float* __restrict__ A,
                       const float* __restrict__ B,
                       const float* __restrict__ C,
                       float* __restrict__ out,
                       long long n_edges)
{
    // csd[m][p][n] = {C[m][n][p], C[m][n][p]} packed; n padded to 8 -> each
    // (m,p) column is 64B-aligned, loadable as 2x LDS.128 + 1x LDS.64.
    __shared__ __align__(16) u64 csd[M1][MP][8];

    int t = threadIdx.x;
    if (t < M1 * M2 * MP) {
        int m = t / 25, n = (t / 5) % 5, p = t % 5;
        float v = C[t];                      // t = (m*5 + n)*5 + p
        csd[m][p][n] = pack2(v, v);
    }
    __syncthreads();

    long long tid = (long long)blockIdx.x * TPB + t;
    long long e0  = tid * EPT;

    if (e0 + EPT <= n_edges) {
        size_t baseA = (size_t)e0 * M1;      // 10 contiguous floats (2 edges)
        size_t baseB = (size_t)e0 * M2;
        size_t baseO = (size_t)e0 * MP;

        // ---- load: 5+5 LDG.64, front-batched ----
        const float2* A2 = reinterpret_cast<const float2*>(A + baseA);
        const float2* B2 = reinterpret_cast<const float2*>(B + baseB);
        float2 av[5], bv[5];
#pragma unroll
        for (int i = 0; i < 5; i++) { av[i] = __ldcs(A2 + i); bv[i] = __ldcs(B2 + i); }

        // ---- pack {edge0, edge1} pairs ----
        // edge0 comps: av0.x av0.y av1.x av1.y av2.x ; edge1: av2.y av3.x av3.y av4.x av4.y
        u64 ap[5], bp[5];
        ap[0] = pack2(av[0].x, av[2].y);  bp[0] = pack2(bv[0].x, bv[2].y);
        ap[1] = pack2(av[0].y, av[3].x);  bp[1] = pack2(bv[0].y, bv[3].x);
        ap[2] = pack2(av[1].x, av[3].y);  bp[2] = pack2(bv[1].x, bv[3].y);
        ap[3] = pack2(av[1].y, av[4].x);  bp[3] = pack2(bv[1].y, bv[4].x);
        ap[4] = pack2(av[2].x, av[4].y);  bp[4] = pack2(bv[2].x, bv[4].y);

        u64 acc[5];
#pragma unroll
        for (int p = 0; p < 5; p++) acc[p] = 0ULL;

#pragma unroll
        for (int m = 0; m < M1; m++) {
            u64 am = ap[m];
#pragma unroll
            for (int p = 0; p < MP; p++) {
                const ulonglong2* c2 =
                    reinterpret_cast<const ulonglong2*>(&csd[m][p][0]);
                ulonglong2 c01 = c2[0];      // LDS.128 (broadcast)
                ulonglong2 c23 = c2[1];      // LDS.128
                u64        c4  = csd[m][p][4];

                u64 d = mul2(c01.x, bp[0]);
                d = fma2(bp[1], c01.y, d);
                d = fma2(bp[2], c23.x, d);
                d = fma2(bp[3], c23.y, d);
                d = fma2(bp[4], c4,    d);

                acc[p] = fma2(am, d, acc[p]);
            }
        }

        // ---- unpack + store: 5 STG.64 ----
        float o0[5], o1[5];
#pragma unroll
        for (int p = 0; p < 5; p++) unpack2(acc[p], o0[p], o1[p]);

        float2* O2 = reinterpret_cast<float2*>(out + baseO);
        float2 ov[5];
        ov[0] = make_float2(o0[0], o0[1]);
        ov[1] = make_float2(o0[2], o0[3]);
        ov[2] = make_float2(o0[4], o1[0]);
        ov[3] = make_float2(o1[1], o1[2]);
        ov[4] = make_float2(o1[3], o1[4]);
#pragma unroll
        for (int i = 0; i < 5; i++) __stcs(O2 + i, ov[i]);
    } else if (e0 < n_edges) {
        // ---- tail (scalar; not taken for N = 16,777,216) ----
        for (long long e = e0; e < n_edges; e++) {
            float a[5], b[5];
#pragma unroll
            for (int k = 0; k < 5; k++) { a[k] = A[e * 5 + k]; b[k] = B[e * 5 + k]; }
#pragma unroll
            for (int p = 0; p < MP; p++) {
                float s = 0.0f;
#pragma unroll
                for (int m = 0; m < M1; m++) {
                    float d = 0.0f;
#pragma unroll
                    for (int n = 0; n < M2; n++) {
                        float clo, chi; unpack2(csd[m][p][n], clo, chi);
                        d = fmaf(b[n], clo, d);
                    }
                    s = fmaf(a[m], d, s);
                }
                out[e * 5 + p] = s;
            }
        }
    }
}

extern "C" void kernel_launch(void* const* d_in, const int* in_sizes, int n_in,
                              void* d_out, int out_size)
{
    const float* A = (const float*)d_in[0];
    const float* B = (const float*)d_in[1];
    const float* C = (const float*)d_in[2];
    float* out = (float*)d_out;

    long long n_edges = (long long)in_sizes[0] / M1;
    long long n_threads = (n_edges + EPT - 1) / EPT;
    int blocks = (int)((n_threads + TPB - 1) / TPB);

    cg_combine_kernel<<<blocks, TPB>>>(A, B, C, out, n_edges);
}

// round 8
// speedup vs baseline: 1.3115x; 1.3115x over previous
#include <cuda_runtime.h>

// out[i,p] = sum_{m,n} A[i,m] * B[i,n] * C[m,n,p]   (M1=M2=MP=5)
//
// Round-8 = round-3 body (direct float2 streaming IO, EPT=2, 64-reg cap,
// 4 CTAs/SM — best so far at 180us) with C moved to __constant__ memory.
// Round-3 was L1tex-wavefront-bound; its single largest L1 component was
// 50 LDS/thread for C columns. Constant-bank loads (LDC/LDCU) use a separate
// port, removing C from the L1 crossbar entirely. C is populated by a
// graph-capturable device-to-device cudaMemcpyToSymbolAsync.

#define M1 5
#define M2 5
#define MP 5
#define EPT 2
#define TPB 256

__constant__ float cC[M1 * M2 * MP];   // cC[(m*5 + n)*5 + p]

__device__ __forceinline__ float cc(int m, int n, int p) {
    return cC[(m * M2 + n) * MP + p];
}

__global__ __launch_bounds__(TPB, 4)
void cg_combine_kernel(const float* __restrict__ A,
                       const float* __restrict__ B,
                       float* __restrict__ out,
                       long long n_edges)
{
    int t = threadIdx.x;
    long long tid = (long long)blockIdx.x * TPB + t;
    long long e0  = tid * EPT;

    if (e0 + EPT <= n_edges) {
        // ---- fast path: float2-vectorized streaming IO ----
        size_t baseA = (size_t)e0 * M1;
        size_t baseB = (size_t)e0 * M2;
        size_t baseO = (size_t)e0 * MP;

        float a[EPT * M1];   // a[edge*5 + comp]... packed as 2x5 below
        float b[EPT * M2];

        {
            const float2* A2 = reinterpret_cast<const float2*>(A + baseA);
            const float2* B2 = reinterpret_cast<const float2*>(B + baseB);
            float2 av[5], bv[5];
#pragma unroll
            for (int i = 0; i < 5; i++) { av[i] = __ldcs(A2 + i); bv[i] = __ldcs(B2 + i); }
#pragma unroll
            for (int i = 0; i < 5; i++) {
                a[i * 2 + 0] = av[i].x; a[i * 2 + 1] = av[i].y;
                b[i * 2 + 0] = bv[i].x; b[i * 2 + 1] = bv[i].y;
            }
            // a[k]: k<5 -> edge0 comp k ; k>=5 -> edge1 comp k-5 after relayout:
            // contiguous layout is [e0c0..e0c4, e1c0..e1c4] == exactly a[0..9]
        }

        float acc[EPT * MP];
#pragma unroll
        for (int i = 0; i < EPT * MP; i++) acc[i] = 0.0f;

#pragma unroll
        for (int m = 0; m < M1; m++) {
            float am0 = a[m];          // edge0 component m
            float am1 = a[M1 + m];     // edge1 component m
#pragma unroll
            for (int p = 0; p < MP; p++) {
                // C column (m, :, p) from constant bank — off the L1 crossbar
                float c0 = cc(m, 0, p);
                float c1 = cc(m, 1, p);
                float c2 = cc(m, 2, p);
                float c3 = cc(m, 3, p);
                float c4 = cc(m, 4, p);

                float d0 = c0 * b[0];
                float d1 = c0 * b[M2 + 0];
                d0 = fmaf(b[1],      c1, d0);
                d1 = fmaf(b[M2 + 1], c1, d1);
                d0 = fmaf(b[2],      c2, d0);
                d1 = fmaf(b[M2 + 2], c2, d1);
                d0 = fmaf(b[3],      c3, d0);
                d1 = fmaf(b[M2 + 3], c3, d1);
                d0 = fmaf(b[4],      c4, d0);
                d1 = fmaf(b[M2 + 4], c4, d1);

                acc[p]      = fmaf(am0, d0, acc[p]);
                acc[MP + p] = fmaf(am1, d1, acc[MP + p]);
            }
        }

        {
            float2* O2 = reinterpret_cast<float2*>(out + baseO);
            float2 ov[5];
#pragma unroll
            for (int i = 0; i < 5; i++) {
                ov[i].x = acc[i * 2 + 0];
                ov[i].y = acc[i * 2 + 1];
            }
#pragma unroll
            for (int i = 0; i < 5; i++) __stcs(O2 + i, ov[i]);
        }
    } else if (e0 < n_edges) {
        // ---- tail path (scalar; not taken for N = 16,777,216) ----
        for (long long e = e0; e < n_edges; e++) {
            float a[M1], b[M2];
#pragma unroll
            for (int k = 0; k < 5; k++) { a[k] = A[e * 5 + k]; b[k] = B[e * 5 + k]; }
#pragma unroll
            for (int p = 0; p < MP; p++) {
                float s = 0.0f;
#pragma unroll
                for (int m = 0; m < M1; m++) {
                    float d = 0.0f;
#pragma unroll
                    for (int n = 0; n < M2; n++) d = fmaf(b[n], cc(m, n, p), d);
                    s = fmaf(a[m], d, s);
                }
                out[e * 5 + p] = s;
            }
        }
    }
}

extern "C" void kernel_launch(void* const* d_in, const int* in_sizes, int n_in,
                              void* d_out, int out_size)
{
    const float* A = (const float*)d_in[0];
    const float* B = (const float*)d_in[1];
    const float* C = (const float*)d_in[2];
    float* out = (float*)d_out;

    // Populate the constant bank: device-to-device async copy (graph-capturable
    // memcpy node, no allocation, runs every call -> deterministic).
    cudaMemcpyToSymbolAsync(cC, C, M1 * M2 * MP * sizeof(float), 0,
                            cudaMemcpyDeviceToDevice, 0);

    long long n_edges = (long long)in_sizes[0] / M1;
    long long n_threads = (n_edges + EPT - 1) / EPT;
    int blocks = (int)((n_threads + TPB - 1) / TPB);

    cg_combine_kernel<<<blocks, TPB>>>(A, B, out, n_edges);
}